// round 2
// baseline (speedup 1.0000x reference)
#include <cuda_runtime.h>
#include <cuda_bf16.h>
#include <cstdint>

// ---------------- problem constants ----------------
#define NPRED 1200      // 4*300
#define NTGT  256
#define NCLS  80
#define HW    128
#define SRC   256
#define PIX   16384     // 128*128
#define KTOT  16384
#define MROWS 2400      // rows 0..1199: X (logits), 1200..2399: sigmoid(X)

// ---------------- GEMM config ----------------
#define BM 128
#define BN 128
#define BK 32
#define SPLITK 4
#define KSPLIT (KTOT / SPLITK)   // 4096
#define KT_PER (KSPLIT / BK)     // 128
#define MTILES 19                // ceil(2400/128)
#define SMPAD 40                 // 32 + 8 bf16 pad -> 80B row stride (16B aligned, conflict-free frags)

// ---------------- scratch (device globals; no allocs) ----------------
__device__ __align__(16) __nv_bfloat16 g_Ab[(size_t)MROWS * KTOT];   // 78.6 MB
__device__ __align__(16) __nv_bfloat16 g_Tb[(size_t)NTGT * KTOT];    //  8.4 MB
__device__ __align__(16) float g_D[SPLITK][(size_t)MROWS * NTGT];    //  9.8 MB
__device__ float g_tsum[NTGT];
__device__ float g_ssum[NPRED];    // sum softplus(X) per pred row
__device__ float g_sigsum[NPRED];  // sum sigmoid(X) per pred row

// ---------------- helpers ----------------
template <int NW>
__device__ __forceinline__ float block_sum(float v) {
    __shared__ float red[NW];
    int lane = threadIdx.x & 31, w = threadIdx.x >> 5;
#pragma unroll
    for (int o = 16; o > 0; o >>= 1) v += __shfl_down_sync(0xffffffffu, v, o);
    if (lane == 0) red[w] = v;
    __syncthreads();
    if (w == 0) {
        v = (lane < NW) ? red[lane] : 0.f;
#pragma unroll
        for (int o = NW / 2; o > 0; o >>= 1) v += __shfl_down_sync(0xffffffffu, v, o);
    }
    return v;  // valid on thread 0
}

// jax.image.resize(antialias=True) 2x-down triangle taps, edge-renormalized.
__device__ __forceinline__ void make_taps(int i, int* j, float* w) {
    const float bw[4] = {0.125f, 0.375f, 0.375f, 0.125f};
    float s = 0.f;
#pragma unroll
    for (int d = 0; d < 4; ++d) {
        int jj = 2 * i - 1 + d;
        bool ok = (jj >= 0) && (jj < SRC);
        j[d] = ok ? jj : 0;
        w[d] = ok ? bw[d] : 0.f;
        s += w[d];
    }
    float inv = 1.f / s;
#pragma unroll
    for (int d = 0; d < 4; ++d) w[d] *= inv;
}

__device__ __forceinline__ void cp16(void* dst, const void* src, int nbytes) {
    unsigned sd = (unsigned)__cvta_generic_to_shared(dst);
    asm volatile("cp.async.cg.shared.global [%0], [%1], 16, %2;\n" ::"r"(sd), "l"(src), "r"(nbytes));
}

__device__ __forceinline__ void mma16816(float* d, const uint32_t* a, const uint32_t* b) {
    asm volatile(
        "mma.sync.aligned.m16n8k16.row.col.f32.bf16.bf16.f32 "
        "{%0,%1,%2,%3}, {%4,%5,%6,%7}, {%8,%9}, {%0,%1,%2,%3};\n"
        : "+f"(d[0]), "+f"(d[1]), "+f"(d[2]), "+f"(d[3])
        : "r"(a[0]), "r"(a[1]), "r"(a[2]), "r"(a[3]), "r"(b[0]), "r"(b[1]));
}

// ---------------- kernel 1: resize targets 256x256 -> 128x128 (bf16) + tsum ----------------
__global__ __launch_bounds__(128) void k_resize(const float* __restrict__ tgt) {
    int m = blockIdx.x;
    int x = threadIdx.x;  // one output column per thread
    const float* src = tgt + (size_t)m * (SRC * SRC);
    __nv_bfloat16* dst = g_Tb + (size_t)m * PIX;

    int jx[4]; float wx[4];
    make_taps(x, jx, wx);

    float sum = 0.f;
    for (int y = 0; y < HW; ++y) {
        int jy[4]; float wy[4];
        make_taps(y, jy, wy);
        float v = 0.f;
#pragma unroll
        for (int dy = 0; dy < 4; ++dy) {
            const float* row = src + (size_t)jy[dy] * SRC;
            float h = wx[0] * row[jx[0]] + wx[1] * row[jx[1]] +
                      wx[2] * row[jx[2]] + wx[3] * row[jx[3]];
            v += wy[dy] * h;
        }
        dst[y * HW + x] = __float2bfloat16_rn(v);
        sum += v;
    }
    float tot = block_sum<4>(sum);
    if (threadIdx.x == 0) g_tsum[m] = tot;
}

// ---------------- kernel 2: pred_masks -> bf16 X & sigmoid(X); rowsums ----------------
__global__ __launch_bounds__(256) void k_convert(const float* __restrict__ pm) {
    int n = blockIdx.x;
    const float4* src = (const float4*)(pm + (size_t)n * PIX);
    uint32_t* dx = (uint32_t*)(g_Ab + (size_t)n * KTOT);
    uint32_t* ds = (uint32_t*)(g_Ab + (size_t)(NPRED + n) * KTOT);

    float ssum = 0.f, gsum = 0.f;
    for (int i = threadIdx.x; i < PIX / 4; i += 256) {
        float4 v = src[i];
        float xs[4] = {v.x, v.y, v.z, v.w};
        float sg[4], sp[4];
#pragma unroll
        for (int c = 0; c < 4; ++c) {
            float xv = xs[c];
            sg[c] = 1.f / (1.f + __expf(-xv));
            // softplus(x) = max(x,0) + log1p(exp(-|x|))
            sp[c] = fmaxf(xv, 0.f) + log1pf(__expf(-fabsf(xv)));
            gsum += sg[c];
            ssum += sp[c];
        }
        __nv_bfloat162 x01 = __floats2bfloat162_rn(xs[0], xs[1]);
        __nv_bfloat162 x23 = __floats2bfloat162_rn(xs[2], xs[3]);
        __nv_bfloat162 s01 = __floats2bfloat162_rn(sg[0], sg[1]);
        __nv_bfloat162 s23 = __floats2bfloat162_rn(sg[2], sg[3]);
        dx[2 * i]     = *(uint32_t*)&x01;
        dx[2 * i + 1] = *(uint32_t*)&x23;
        ds[2 * i]     = *(uint32_t*)&s01;
        ds[2 * i + 1] = *(uint32_t*)&s23;
    }
    float s_tot = block_sum<8>(ssum);
    __syncthreads();
    float g_tot = block_sum<8>(gsum);
    if (threadIdx.x == 0) {
        g_ssum[n] = s_tot;
        g_sigsum[n] = g_tot;
    }
}

// ---------------- kernel 3: GEMM  D[s] = A(2400xK_split) @ T^T(256xK_split) ----------------
__global__ __launch_bounds__(256) void k_gemm() {
    __shared__ __nv_bfloat16 As[2][BM][SMPAD];
    __shared__ __nv_bfloat16 Bs[2][BN][SMPAD];

    const int m0 = blockIdx.x * BM;
    const int n0 = blockIdx.y * BN;
    const int kz = blockIdx.z;
    const int kbase = kz * KSPLIT;

    const int tid = threadIdx.x;
    const int lane = tid & 31;
    const int wid = tid >> 5;
    const int wm = wid & 1;   // 2 warp-rows of 64
    const int wn = wid >> 1;  // 4 warp-cols of 32
    const int g = lane >> 2;
    const int t = lane & 3;

    auto load_tiles = [&](int buf, int kt) {
        int k0 = kbase + kt * BK;
        int r = tid >> 2;
        int c = (tid & 3) << 3;
#pragma unroll
        for (int h = 0; h < 2; ++h) {
            int rr = r + h * 64;
            int grow = m0 + rr;
            const __nv_bfloat16* sa =
                g_Ab + (size_t)(grow < MROWS ? grow : 0) * KTOT + k0 + c;
            cp16(&As[buf][rr][c], sa, grow < MROWS ? 16 : 0);
            const __nv_bfloat16* sb = g_Tb + (size_t)(n0 + rr) * KTOT + k0 + c;
            cp16(&Bs[buf][rr][c], sb, 16);
        }
    };

    float acc[4][4][4];
#pragma unroll
    for (int i = 0; i < 4; ++i)
#pragma unroll
        for (int j = 0; j < 4; ++j)
#pragma unroll
            for (int k = 0; k < 4; ++k) acc[i][j][k] = 0.f;

    load_tiles(0, 0);
    asm volatile("cp.async.commit_group;\n");

#pragma unroll 1
    for (int kt = 0; kt < KT_PER; ++kt) {
        int buf = kt & 1;
        if (kt + 1 < KT_PER) {
            load_tiles(buf ^ 1, kt + 1);
            asm volatile("cp.async.commit_group;\n");
            asm volatile("cp.async.wait_group 1;\n");
        } else {
            asm volatile("cp.async.wait_group 0;\n");
        }
        __syncthreads();

#pragma unroll
        for (int ks = 0; ks < BK; ks += 16) {
            uint32_t af[4][4];
            uint32_t bf[4][2];
#pragma unroll
            for (int fm = 0; fm < 4; ++fm) {
                int r = wm * 64 + fm * 16;
                af[fm][0] = *(const uint32_t*)&As[buf][r + g][ks + 2 * t];
                af[fm][1] = *(const uint32_t*)&As[buf][r + g + 8][ks + 2 * t];
                af[fm][2] = *(const uint32_t*)&As[buf][r + g][ks + 8 + 2 * t];
                af[fm][3] = *(const uint32_t*)&As[buf][r + g + 8][ks + 8 + 2 * t];
            }
#pragma unroll
            for (int fn = 0; fn < 4; ++fn) {
                int c = wn * 32 + fn * 8;
                bf[fn][0] = *(const uint32_t*)&Bs[buf][c + g][ks + 2 * t];
                bf[fn][1] = *(const uint32_t*)&Bs[buf][c + g][ks + 8 + 2 * t];
            }
#pragma unroll
            for (int fm = 0; fm < 4; ++fm)
#pragma unroll
                for (int fn = 0; fn < 4; ++fn) mma16816(acc[fm][fn], af[fm], bf[fn]);
        }
        __syncthreads();
    }

    // epilogue: D[kz][row][col]
    float* Dp = g_D[kz];
#pragma unroll
    for (int fm = 0; fm < 4; ++fm) {
        int rowb = m0 + wm * 64 + fm * 16;
        int r0 = rowb + g;
        int r1 = rowb + g + 8;
#pragma unroll
        for (int fn = 0; fn < 4; ++fn) {
            int col = n0 + wn * 32 + fn * 8 + 2 * t;
            if (r0 < MROWS)
                *(float2*)&Dp[(size_t)r0 * NTGT + col] =
                    make_float2(acc[fm][fn][0], acc[fm][fn][1]);
            if (r1 < MROWS)
                *(float2*)&Dp[(size_t)r1 * NTGT + col] =
                    make_float2(acc[fm][fn][2], acc[fm][fn][3]);
        }
    }
}

// ---------------- kernel 4: assemble final cost matrix ----------------
__global__ __launch_bounds__(256) void k_assemble(const float* __restrict__ logits,
                                                  const float* __restrict__ pboxes,
                                                  const int* __restrict__ ids,
                                                  const float* __restrict__ tboxes,
                                                  float* __restrict__ out) {
    int n = blockIdx.x;
    int m = threadIdx.x;

    float4 pb = ((const float4*)pboxes)[n];
    float4 tb = ((const float4*)tboxes)[m];

    // L1 in cxcywh space
    float cbbox = fabsf(pb.x - tb.x) + fabsf(pb.y - tb.y) +
                  fabsf(pb.z - tb.z) + fabsf(pb.w - tb.w);

    // giou in xyxy
    float p1x = pb.x - 0.5f * pb.z, p1y = pb.y - 0.5f * pb.w;
    float p2x = pb.x + 0.5f * pb.z, p2y = pb.y + 0.5f * pb.w;
    float t1x = tb.x - 0.5f * tb.z, t1y = tb.y - 0.5f * tb.w;
    float t2x = tb.x + 0.5f * tb.z, t2y = tb.y + 0.5f * tb.w;
    float area1 = (p2x - p1x) * (p2y - p1y);
    float area2 = (t2x - t1x) * (t2y - t1y);
    float iw = fminf(p2x, t2x) - fmaxf(p1x, t1x);
    float ih = fminf(p2y, t2y) - fmaxf(p1y, t1y);
    iw = fmaxf(iw, 0.f); ih = fmaxf(ih, 0.f);
    float inter = iw * ih;
    float uni = area1 + area2 - inter;
    float iou = inter / uni;
    float ew = fmaxf(p2x, t2x) - fminf(p1x, t1x);
    float eh = fmaxf(p2y, t2y) - fminf(p1y, t1y);
    ew = fmaxf(ew, 0.f); eh = fmaxf(eh, 0.f);
    float ae = ew * eh;
    float cgiou = -(iou - (ae - uni) / ae);

    int id = ids[m];
    float lg = logits[(size_t)n * NCLS + id];
    float cclass = -1.f / (1.f + expf(-lg));

    size_t ix = (size_t)n * NTGT + m;
    size_t is = (size_t)(NPRED + n) * NTGT + m;
    float dX = g_D[0][ix] + g_D[1][ix] + g_D[2][ix] + g_D[3][ix];
    float dS = g_D[0][is] + g_D[1][is] + g_D[2][is] + g_D[3][is];

    float cmask = (g_ssum[n] - dX) * (1.f / (float)PIX);
    float denom = fmaxf(g_sigsum[n] + g_tsum[m], 1e-6f) + 1.f;
    float cdice = -(2.f * dS + 1.f) / denom;

    out[ix] = 5.f * cbbox + 2.f * cgiou + 2.f * cclass + 2.f * cmask + 2.f * cdice;
}

// ---------------- launch ----------------
extern "C" void kernel_launch(void* const* d_in, const int* in_sizes, int n_in,
                              void* d_out, int out_size) {
    const float* logits = (const float*)d_in[0];   // [4,300,80]
    const float* pboxes = (const float*)d_in[1];   // [4,300,4]
    const float* pmasks = (const float*)d_in[2];   // [4,300,128,128]
    const int*   ids    = (const int*)d_in[3];     // [256] int32
    const float* tboxes = (const float*)d_in[4];   // [256,4]
    const float* tmasks = (const float*)d_in[5];   // [256,256,256]
    float* out = (float*)d_out;                    // [4,300,256]

    k_resize<<<NTGT, 128>>>(tmasks);
    k_convert<<<NPRED, 256>>>(pmasks);
    dim3 gg(MTILES, NTGT / BN, SPLITK);
    k_gemm<<<gg, 256>>>();
    k_assemble<<<NPRED, NTGT>>>(logits, pboxes, ids, tboxes, out);
}

// round 4
// speedup vs baseline: 2.0609x; 2.0609x over previous
#include <cuda_runtime.h>
#include <cuda_bf16.h>
#include <cstdint>

// ---------------- problem constants ----------------
#define NPRED 1200
#define NTGT  256
#define NCLS  80
#define HW    128
#define SRC   256
#define PIX   16384
#define KTOT  16384
#define MROWS 2400      // rows 0..1199: X (logits), 1200..2399: sigmoid(X)

// ---------------- GEMM config (legacy mma.sync, sm_100-safe) ----------------
#define BM     128
#define BN     256
#define BK     64                 // 128B rows in smem
#define SPLITK 7
#define KS     2368               // ceil(16384/7/64)*64 ; last split gets 2176
#define MT     19                 // ceil(2400/128)
#define ABYTES (BM * 128)         // 16 KB
#define BBYTES (BN * 128)         // 32 KB
#define STGB   (ABYTES + BBYTES)  // 48 KB
#define SMEMSZ (1024 + 2 * STGB)  // align slack + 2 stages

// ---------------- scratch (device globals; no allocs) ----------------
__device__ __align__(16) __nv_bfloat16 g_Ab[(size_t)MROWS * KTOT];   // 78.6 MB
__device__ __align__(16) __nv_bfloat16 g_Tb[(size_t)NTGT * KTOT];    //  8.4 MB
__device__ __align__(16) float g_D[SPLITK][(size_t)MROWS * NTGT];    // 17.2 MB
__device__ float g_tsum4[NTGT * 4];
__device__ float g_ssum[NPRED];
__device__ float g_sigsum[NPRED];

// ---------------- PTX helpers ----------------
__device__ __forceinline__ uint32_t smem_u32(const void* p) {
    uint32_t a;
    asm("{ .reg .u64 t; cvta.to.shared.u64 t, %1; cvt.u32.u64 %0, t; }" : "=r"(a) : "l"(p));
    return a;
}
__device__ __forceinline__ void cp16(uint32_t sdst, const void* src, int nbytes) {
    asm volatile("cp.async.cg.shared.global [%0], [%1], 16, %2;\n"
                 ::"r"(sdst), "l"(src), "r"(nbytes));
}
__device__ __forceinline__ void ldsm4(uint32_t* r, uint32_t addr) {
    asm volatile("ldmatrix.sync.aligned.m8n8.x4.shared.b16 {%0,%1,%2,%3}, [%4];"
                 : "=r"(r[0]), "=r"(r[1]), "=r"(r[2]), "=r"(r[3]) : "r"(addr));
}
__device__ __forceinline__ void mma16816(float* d, const uint32_t* a, const uint32_t* b) {
    asm volatile(
        "mma.sync.aligned.m16n8k16.row.col.f32.bf16.bf16.f32 "
        "{%0,%1,%2,%3}, {%4,%5,%6,%7}, {%8,%9}, {%0,%1,%2,%3};\n"
        : "+f"(d[0]), "+f"(d[1]), "+f"(d[2]), "+f"(d[3])
        : "r"(a[0]), "r"(a[1]), "r"(a[2]), "r"(a[3]), "r"(b[0]), "r"(b[1]));
}

template <int NW>
__device__ __forceinline__ float block_sum(float v) {
    __shared__ float red[NW];
    int lane = threadIdx.x & 31, w = threadIdx.x >> 5;
#pragma unroll
    for (int o = 16; o > 0; o >>= 1) v += __shfl_down_sync(0xffffffffu, v, o);
    if (lane == 0) red[w] = v;
    __syncthreads();
    if (w == 0) {
        v = (lane < NW) ? red[lane] : 0.f;
#pragma unroll
        for (int o = NW / 2; o > 0; o >>= 1) v += __shfl_down_sync(0xffffffffu, v, o);
    }
    return v;  // valid on thread 0
}

// jax.image.resize(antialias=True) 2x-down triangle taps, edge-renormalized.
__device__ __forceinline__ void make_taps(int i, int* j, float* w) {
    const float bw[4] = {0.125f, 0.375f, 0.375f, 0.125f};
    float s = 0.f;
#pragma unroll
    for (int d = 0; d < 4; ++d) {
        int jj = 2 * i - 1 + d;
        bool ok = (jj >= 0) && (jj < SRC);
        j[d] = ok ? jj : 0;
        w[d] = ok ? bw[d] : 0.f;
        s += w[d];
    }
    float inv = 1.f / s;
#pragma unroll
    for (int d = 0; d < 4; ++d) w[d] *= inv;
}

// ---------------- kernel 1: resize targets 256x256 -> 128x128 (bf16) + tsum ----------------
__global__ __launch_bounds__(128) void k_resize(const float* __restrict__ tgt) {
    int m = blockIdx.x;
    int chunk = blockIdx.y;   // 4 row-chunks of 32
    int x = threadIdx.x;
    const float* src = tgt + (size_t)m * (SRC * SRC);
    __nv_bfloat16* dst = g_Tb + (size_t)m * PIX;

    int jx[4]; float wx[4];
    make_taps(x, jx, wx);

    float sum = 0.f;
    int y0 = chunk * 32;
    for (int y = y0; y < y0 + 32; ++y) {
        int jy[4]; float wy[4];
        make_taps(y, jy, wy);
        float v = 0.f;
#pragma unroll
        for (int dy = 0; dy < 4; ++dy) {
            const float* row = src + (size_t)jy[dy] * SRC;
            float h = wx[0] * row[jx[0]] + wx[1] * row[jx[1]] +
                      wx[2] * row[jx[2]] + wx[3] * row[jx[3]];
            v += wy[dy] * h;
        }
        dst[y * HW + x] = __float2bfloat16_rn(v);
        sum += v;
    }
    float tot = block_sum<4>(sum);
    if (threadIdx.x == 0) g_tsum4[m * 4 + chunk] = tot;
}

// ---------------- kernel 2: pred_masks -> bf16 X & sigmoid(X); rowsums ----------------
__global__ __launch_bounds__(256) void k_convert(const float* __restrict__ pm) {
    int n = blockIdx.x;
    const float4* src = (const float4*)(pm + (size_t)n * PIX);
    uint32_t* dx = (uint32_t*)(g_Ab + (size_t)n * KTOT);
    uint32_t* ds = (uint32_t*)(g_Ab + (size_t)(NPRED + n) * KTOT);

    float ssum = 0.f, gsum = 0.f;
    for (int i = threadIdx.x; i < PIX / 4; i += 256) {
        float4 v = src[i];
        float xs[4] = {v.x, v.y, v.z, v.w};
        float sg[4];
#pragma unroll
        for (int c = 0; c < 4; ++c) {
            float xv = xs[c];
            sg[c] = 1.f / (1.f + __expf(-xv));
            gsum += sg[c];
            ssum += fmaxf(xv, 0.f) + log1pf(__expf(-fabsf(xv)));  // softplus
        }
        __nv_bfloat162 x01 = __floats2bfloat162_rn(xs[0], xs[1]);
        __nv_bfloat162 x23 = __floats2bfloat162_rn(xs[2], xs[3]);
        __nv_bfloat162 s01 = __floats2bfloat162_rn(sg[0], sg[1]);
        __nv_bfloat162 s23 = __floats2bfloat162_rn(sg[2], sg[3]);
        dx[2 * i]     = *(uint32_t*)&x01;
        dx[2 * i + 1] = *(uint32_t*)&x23;
        ds[2 * i]     = *(uint32_t*)&s01;
        ds[2 * i + 1] = *(uint32_t*)&s23;
    }
    float s_tot = block_sum<8>(ssum);
    __syncthreads();
    float g_tot = block_sum<8>(gsum);
    if (threadIdx.x == 0) {
        g_ssum[n] = s_tot;
        g_sigsum[n] = g_tot;
    }
}

// ---------------- kernel 3: GEMM D[kz] = A(128 rows x K) @ T^T(256 x K), ldmatrix+mma ----------------
__global__ __launch_bounds__(256, 1) void k_gemm() {
    extern __shared__ char smem[];
    const uint32_t tiles = (smem_u32(smem) + 1023u) & ~1023u;

    const int tid = threadIdx.x;
    const int lane = tid & 31;
    const int wid = tid >> 5;
    const int wm = wid & 1;    // 2 warp-rows of 64
    const int wn = wid >> 1;   // 4 warp-cols of 64
    const int m0 = blockIdx.x * BM;
    const int kz = blockIdx.y;
    const int kbase = kz * KS;
    const int kend = min(kbase + KS, KTOT);
    const int NT = (kend - kbase) / BK;   // 37 or 34

    // ---- loader lambda ----
    auto load_tile = [&](int j) {
        int stage = j & 1;
        uint32_t ab = tiles + stage * STGB;
        uint32_t bb = ab + ABYTES;
        int k0 = kbase + j * BK;
        // A: 1024 chunks of 16B
#pragma unroll
        for (int i = 0; i < 4; ++i) {
            int idx = tid + (i << 8);
            int row = idx >> 3, c16 = idx & 7;
            int grow = m0 + row;
            const void* src = g_Ab + (size_t)(grow < MROWS ? grow : 0) * KTOT + k0 + c16 * 8;
            uint32_t off = (uint32_t)(row * 128 + ((c16 * 16) ^ ((row & 7) << 4)));
            cp16(ab + off, src, grow < MROWS ? 16 : 0);
        }
        // B: 2048 chunks of 16B
#pragma unroll
        for (int i = 0; i < 8; ++i) {
            int idx = tid + (i << 8);
            int row = idx >> 3, c16 = idx & 7;
            const void* src = g_Tb + (size_t)row * KTOT + k0 + c16 * 8;
            uint32_t off = (uint32_t)(row * 128 + ((c16 * 16) ^ ((row & 7) << 4)));
            cp16(bb + off, src, 16);
        }
        asm volatile("cp.async.commit_group;\n" ::: "memory");
    };

    // ---- per-thread ldmatrix base addresses (row part + its constant XOR) ----
    // A frag (mb,kb): row = wm*64 + mb*16 + (lane&7) + (lane&8); colb = kb*32 + ((lane>>4)&1)*16
    const int arow = wm * 64 + (lane & 7) + (lane & 8);
    const uint32_t acol0 = (uint32_t)(((lane >> 4) & 1) * 16);
    // B frag pair p (n-blocks 2p,2p+1) at kb: row = wn*64 + p*16 + (lane&7) + ((lane>>1)&8); colb = kb*32 + (lane&8)*2
    const int brow0 = wn * 64 + (lane & 7) + ((lane >> 1) & 8);
    const uint32_t bcol0 = (uint32_t)((lane & 8) * 2);

    float acc[4][8][4];
#pragma unroll
    for (int a = 0; a < 4; ++a)
#pragma unroll
        for (int b = 0; b < 8; ++b)
#pragma unroll
            for (int c = 0; c < 4; ++c) acc[a][b][c] = 0.f;

    load_tile(0);

#pragma unroll 1
    for (int kt = 0; kt < NT; ++kt) {
        if (kt + 1 < NT) {
            load_tile(kt + 1);
            asm volatile("cp.async.wait_group 1;\n" ::: "memory");
        } else {
            asm volatile("cp.async.wait_group 0;\n" ::: "memory");
        }
        __syncthreads();

        int stage = kt & 1;
        uint32_t ab = tiles + stage * STGB;
        uint32_t bb = ab + ABYTES;

#pragma unroll
        for (int kb = 0; kb < 4; ++kb) {
            uint32_t af[4][4], bf[8][2];
            uint32_t acolb = (uint32_t)(kb * 32) + acol0;
            uint32_t bcolb = (uint32_t)(kb * 32) + bcol0;
#pragma unroll
            for (int mb = 0; mb < 4; ++mb) {
                int r = arow + mb * 16;
                ldsm4(af[mb], ab + (uint32_t)(r * 128) + (acolb ^ ((uint32_t)(r & 7) << 4)));
            }
#pragma unroll
            for (int p = 0; p < 4; ++p) {
                int r = brow0 + p * 16;
                uint32_t tmp[4];
                ldsm4(tmp, bb + (uint32_t)(r * 128) + (bcolb ^ ((uint32_t)(r & 7) << 4)));
                bf[2 * p][0] = tmp[0]; bf[2 * p][1] = tmp[1];
                bf[2 * p + 1][0] = tmp[2]; bf[2 * p + 1][1] = tmp[3];
            }
#pragma unroll
            for (int mb = 0; mb < 4; ++mb)
#pragma unroll
                for (int nb = 0; nb < 8; ++nb) mma16816(acc[mb][nb], af[mb], bf[nb]);
        }
        __syncthreads();
    }

    // ---- epilogue ----
    float* Dp = g_D[kz];
    const int trow = lane >> 2;
    const int tcol = (lane & 3) * 2;
#pragma unroll
    for (int mb = 0; mb < 4; ++mb) {
        int r0 = m0 + wm * 64 + mb * 16 + trow;
        int r1 = r0 + 8;
#pragma unroll
        for (int nb = 0; nb < 8; ++nb) {
            int col = wn * 64 + nb * 8 + tcol;
            if (r0 < MROWS)
                *(float2*)&Dp[(size_t)r0 * NTGT + col] = make_float2(acc[mb][nb][0], acc[mb][nb][1]);
            if (r1 < MROWS)
                *(float2*)&Dp[(size_t)r1 * NTGT + col] = make_float2(acc[mb][nb][2], acc[mb][nb][3]);
        }
    }
}

// ---------------- kernel 4: assemble final cost matrix ----------------
__global__ __launch_bounds__(256) void k_assemble(const float* __restrict__ logits,
                                                  const float* __restrict__ pboxes,
                                                  const int* __restrict__ ids,
                                                  const float* __restrict__ tboxes,
                                                  float* __restrict__ out) {
    int n = blockIdx.x;
    int m = threadIdx.x;

    float4 pb = ((const float4*)pboxes)[n];
    float4 tb = ((const float4*)tboxes)[m];

    float cbbox = fabsf(pb.x - tb.x) + fabsf(pb.y - tb.y) +
                  fabsf(pb.z - tb.z) + fabsf(pb.w - tb.w);

    float p1x = pb.x - 0.5f * pb.z, p1y = pb.y - 0.5f * pb.w;
    float p2x = pb.x + 0.5f * pb.z, p2y = pb.y + 0.5f * pb.w;
    float t1x = tb.x - 0.5f * tb.z, t1y = tb.y - 0.5f * tb.w;
    float t2x = tb.x + 0.5f * tb.z, t2y = tb.y + 0.5f * tb.w;
    float area1 = (p2x - p1x) * (p2y - p1y);
    float area2 = (t2x - t1x) * (t2y - t1y);
    float iw = fmaxf(fminf(p2x, t2x) - fmaxf(p1x, t1x), 0.f);
    float ih = fmaxf(fminf(p2y, t2y) - fmaxf(p1y, t1y), 0.f);
    float inter = iw * ih;
    float uni = area1 + area2 - inter;
    float iou = inter / uni;
    float ew = fmaxf(fmaxf(p2x, t2x) - fminf(p1x, t1x), 0.f);
    float eh = fmaxf(fmaxf(p2y, t2y) - fminf(p1y, t1y), 0.f);
    float ae = ew * eh;
    float cgiou = -(iou - (ae - uni) / ae);

    int id = ids[m];
    float lg = logits[(size_t)n * NCLS + id];
    float cclass = -1.f / (1.f + expf(-lg));

    size_t ix = (size_t)n * NTGT + m;
    size_t is = (size_t)(NPRED + n) * NTGT + m;
    float dX = 0.f, dS = 0.f;
#pragma unroll
    for (int s = 0; s < SPLITK; ++s) {
        dX += g_D[s][ix];
        dS += g_D[s][is];
    }

    float tsum = g_tsum4[m * 4] + g_tsum4[m * 4 + 1] + g_tsum4[m * 4 + 2] + g_tsum4[m * 4 + 3];
    float cmask = (g_ssum[n] - dX) * (1.f / (float)PIX);
    float denom = fmaxf(g_sigsum[n] + tsum, 1e-6f) + 1.f;
    float cdice = -(2.f * dS + 1.f) / denom;

    out[ix] = 5.f * cbbox + 2.f * cgiou + 2.f * cclass + 2.f * cmask + 2.f * cdice;
}

// ---------------- launch ----------------
extern "C" void kernel_launch(void* const* d_in, const int* in_sizes, int n_in,
                              void* d_out, int out_size) {
    const float* logits = (const float*)d_in[0];
    const float* pboxes = (const float*)d_in[1];
    const float* pmasks = (const float*)d_in[2];
    const int*   ids    = (const int*)d_in[3];
    const float* tboxes = (const float*)d_in[4];
    const float* tmasks = (const float*)d_in[5];
    float* out = (float*)d_out;

    cudaFuncSetAttribute(k_gemm, cudaFuncAttributeMaxDynamicSharedMemorySize, SMEMSZ);

    k_resize<<<dim3(NTGT, 4), 128>>>(tmasks);
    k_convert<<<NPRED, 256>>>(pmasks);
    k_gemm<<<dim3(MT, SPLITK), 256, SMEMSZ>>>();
    k_assemble<<<NPRED, NTGT>>>(logits, pboxes, ids, tboxes, out);
}